// round 11
// baseline (speedup 1.0000x reference)
#include <cuda_runtime.h>
#include <cstdint>

// Problem constants (B=1, H=8, S=1024, D=64, KG=10)
#define SS    1024
#define DH    64
#define NH    8
#define NKG   10
#define LUTN  2048
#define BM    64
#define BN    64
#define SPLIT 8
#define SKEY  (SS / SPLIT)

// XOR swizzle: maps k-row to an octet shift so mma fragment loads are
// conflict-free for both (k%4) and (k>>2) varying access patterns.
#define SWZ(k) ((((k) ^ ((k) >> 2)) & 3) << 3)

// ---------------------------------------------------------------------------
// Device scratch (static allocations only — no cudaMalloc allowed)
// ---------------------------------------------------------------------------
__device__ float g_lutD[LUTN];                 // plain float tables
__device__ float g_lutE[LUTN];
__device__ float g_rng[4];                     // loD, invhD, loE, invhE
__device__ float g_pacc[SPLIT][NH][SS][DH];    // 16 MB partial accumulators
__device__ float g_pm[SPLIT][NH][SS];
__device__ float g_pl[SPLIT][NH][SS];
__device__ int   g_cnt[SS / BM][NH];           // per-(row-tile, head) arrival counters

// ---------------------------------------------------------------------------
// tf32 + mma helpers
// ---------------------------------------------------------------------------
__device__ __forceinline__ unsigned tf32_of(float x) {
    unsigned u; asm("cvt.rna.tf32.f32 %0, %1;" : "=r"(u) : "f"(x)); return u;
}
__device__ __forceinline__ float tf32f(float x) { return __uint_as_float(tf32_of(x)); }

__device__ __forceinline__ void mma_tf32(
    float* c, unsigned a0, unsigned a1, unsigned a2, unsigned a3,
    unsigned b0, unsigned b1)
{
    asm volatile(
        "mma.sync.aligned.m16n8k8.row.col.f32.tf32.tf32.f32 "
        "{%0,%1,%2,%3}, {%4,%5,%6,%7}, {%8,%9}, {%0,%1,%2,%3};"
        : "+f"(c[0]), "+f"(c[1]), "+f"(c[2]), "+f"(c[3])
        : "r"(a0), "r"(a1), "r"(a2), "r"(a3), "r"(b0), "r"(b1));
}

// smem-resident LUT interpolation: 2 LDS.32 (bank-conflict gather)
__device__ __forceinline__ float lut_bias_s(float x, float lo, float ih,
                                            const float* __restrict__ slut) {
    float u = (x - lo) * ih;
    u = fminf(fmaxf(u, 0.f), (float)(LUTN - 1));
    int ii = min((int)u, LUTN - 2);
    float fr = u - (float)ii;
    float va = slut[ii];
    float vb = slut[ii + 1];
    return fmaf(vb - va, fr, va);
}

// ---------------------------------------------------------------------------
// Kernel 1: build float bias LUTs + zero the group counters.
// bias(x) = W2 @ gelu(W1 @ psi(x) + b1) + b2, psi_k(x) = N(x + b_k; mu_k, s_k)
// Range covers +-12 sigma of every kernel center; outside, psi underflows to
// 0 so clamping to the LUT edge is exact.
// ---------------------------------------------------------------------------
__global__ void build_lut_kernel(
    const float* __restrict__ muD, const float* __restrict__ sgD, const float* __restrict__ bD,
    const float* __restrict__ muE, const float* __restrict__ sgE, const float* __restrict__ bE,
    const float* __restrict__ W1, const float* __restrict__ b1,
    const float* __restrict__ W2, const float* __restrict__ b2)
{
    const int which = blockIdx.x;            // 0 => D, 1 => E
    // zero arrival counters for this launch (runs before attn in-stream)
    if (which == 0 && blockIdx.y == 0 && threadIdx.x < (SS / BM) * NH)
        ((int*)g_cnt)[threadIdx.x] = 0;

    const float* mu = which ? muE : muD;
    const float* sg = which ? sgE : sgD;
    const float* bb = which ? bE  : bD;
    float* lut      = which ? g_lutE : g_lutD;

    float mus[NKG], sgs[NKG], bbs[NKG], inorm[NKG];
    float lo = 1e30f, hi = -1e30f;
    #pragma unroll
    for (int k = 0; k < NKG; ++k) {
        mus[k] = __ldg(&mu[k]); sgs[k] = __ldg(&sg[k]); bbs[k] = __ldg(&bb[k]);
        inorm[k] = 0.3989422804014327f / sgs[k];
        float c = mus[k] - bbs[k];
        lo = fminf(lo, c - 12.f * sgs[k]);
        hi = fmaxf(hi, c + 12.f * sgs[k]);
    }
    float w1[NKG * NKG], bias1[NKG], w2[NKG], bias2;
    #pragma unroll
    for (int i = 0; i < NKG * NKG; ++i) w1[i] = __ldg(&W1[i]);
    #pragma unroll
    for (int i = 0; i < NKG; ++i) { bias1[i] = __ldg(&b1[i]); w2[i] = __ldg(&W2[i]); }
    bias2 = __ldg(&b2[0]);

    const float step = (hi - lo) / (float)(LUTN - 1);
    const int e = blockIdx.y * blockDim.x + threadIdx.x;   // 0..LUTN-1
    if (e < LUTN) {
        float x = lo + step * (float)e;
        float psi[NKG];
        #pragma unroll
        for (int k = 0; k < NKG; ++k) {
            float z = (x + bbs[k] - mus[k]) / sgs[k];
            psi[k] = expf(-0.5f * z * z) * inorm[k];
        }
        float f = bias2;
        #pragma unroll
        for (int l = 0; l < NKG; ++l) {
            float u = bias1[l];
            #pragma unroll
            for (int k = 0; k < NKG; ++k)
                u = fmaf(w1[l * NKG + k], psi[k], u);
            float g = 0.5f * u * (1.0f + erff(u * 0.70710678118654752f));
            f = fmaf(w2[l], g, f);
        }
        lut[e] = f;
    }
    if (e == 0) {
        float invh = (float)(LUTN - 1) / (hi - lo);
        if (which) { g_rng[2] = lo; g_rng[3] = invh; }
        else       { g_rng[0] = lo; g_rng[1] = invh; }
    }
}

// ---------------------------------------------------------------------------
// Kernel 2: tf32 tensor-core flash attention (split-KV partial) + smem LUT
// + fused last-CTA group merge.
// Grid (S/BM, H, SPLIT) = (16, 8, 8). 256 threads = 8 warps in 4x2 (M x N).
// ---------------------------------------------------------------------------
__global__ void __launch_bounds__(256, 2) attn_kernel(
    const float* __restrict__ Q, const float* __restrict__ K, const float* __restrict__ V,
    const float* __restrict__ dist, const float* __restrict__ ener,
    const int* __restrict__ mask, float* __restrict__ out)
{
    extern __shared__ float smem[];
    float* sqt   = smem;             // [k=64][m=64] Q^T tf32:  k*64 + (m ^ SWZ(k))
    float* skt   = smem + 4096;      // [k=64][n=64] K^T tf32:  k*64 + (n ^ SWZ(k))
    float* sv    = smem + 8192;      // [j=64][d=64] V tf32:    j*64 + (d ^ SWZ(j))
    float* spt   = smem + 12288;     // [j=64][m=64] P^T tf32:  j*64 + (m ^ SWZ(j))
    float* slutD = smem + 16384;     // [2048] bias LUT D
    float* slutE = smem + 18432;     // [2048] bias LUT E

    const int t    = threadIdx.x;
    const int lane = t & 31, w = t >> 5;
    const int lk   = lane & 3, lm = lane >> 2;
    const int wm   = w & 3, wn = w >> 2;
    const int m0   = wm << 4;          // warp's row base within tile
    const int nc0  = wn << 5;          // warp's key-col base within tile
    const int head = blockIdx.y;
    const int i0   = blockIdx.x * BM;
    const int z    = blockIdx.z;

    // ---- stage LUTs into shared ----
    for (int i = t; i < LUTN; i += 256) {
        slutD[i] = g_lutD[i];
        slutE[i] = g_lutE[i];
    }

    // ---- stage Q^T (scaled, tf32) ----
    {
        const float qscale = 0.08838834764831845f;   // 1/sqrt(128)
        const float4* qg = (const float4*)(Q + (size_t)(head * SS + i0) * DH);
        for (int idx = t; idx < 1024; idx += 256) {
            int r = idx >> 4, ch = idx & 15;         // coalesced global reads
            float4 v = qg[r * 16 + ch];
            int d0 = ch << 2;
            sqt[(d0 + 0) * 64 + (r ^ SWZ(d0 + 0))] = tf32f(v.x * qscale);
            sqt[(d0 + 1) * 64 + (r ^ SWZ(d0 + 1))] = tf32f(v.y * qscale);
            sqt[(d0 + 2) * 64 + (r ^ SWZ(d0 + 2))] = tf32f(v.z * qscale);
            sqt[(d0 + 3) * 64 + (r ^ SWZ(d0 + 3))] = tf32f(v.w * qscale);
        }
    }
    const float loD = g_rng[0], ihD = g_rng[1], loE = g_rng[2], ihE = g_rng[3];

    float acc[8][4];                  // O accumulator: 8 d-tiles x C-frag
    #pragma unroll
    for (int dt = 0; dt < 8; ++dt)
        #pragma unroll
        for (int q = 0; q < 4; ++q) acc[dt][q] = 0.f;
    float mrow[2] = {-1e30f, -1e30f};   // rows lm, lm+8 (warp-half private)
    float lrow[2] = {0.f, 0.f};

    for (int jt = 0; jt < SKEY / BN; ++jt) {
        const int j0 = z * SKEY + jt * BN;
        __syncthreads();   // previous iteration's PV reads done before restaging

        // ---- stage K^T and V (tf32) ----
        {
            const float4* kg = (const float4*)(K + (size_t)(head * SS + j0) * DH);
            const float4* vg = (const float4*)(V + (size_t)(head * SS + j0) * DH);
            for (int idx = t; idx < 1024; idx += 256) {
                int r = idx >> 4, ch = idx & 15;
                int d0 = ch << 2;
                float4 kv = kg[r * 16 + ch];
                skt[(d0 + 0) * 64 + (r ^ SWZ(d0 + 0))] = tf32f(kv.x);
                skt[(d0 + 1) * 64 + (r ^ SWZ(d0 + 1))] = tf32f(kv.y);
                skt[(d0 + 2) * 64 + (r ^ SWZ(d0 + 2))] = tf32f(kv.z);
                skt[(d0 + 3) * 64 + (r ^ SWZ(d0 + 3))] = tf32f(kv.w);
                float4 vv = vg[r * 16 + ch];
                float4 vt = make_float4(tf32f(vv.x), tf32f(vv.y), tf32f(vv.z), tf32f(vv.w));
                *(float4*)&sv[r * 64 + (d0 ^ SWZ(r))] = vt;
            }
        }
        __syncthreads();

        // ---- prefetch half-0 bias operands (hide DRAM latency under mma) ----
        float2 pd0[4], pe0[4];
        int2   pk0[4];
        {
            size_t rowbase = ((size_t)(head * SS + i0 + m0 + lm)) * SS
                           + (size_t)(j0 + nc0 + (lk << 1));
            #pragma unroll
            for (int nt = 0; nt < 4; ++nt) {
                pd0[nt] = *(const float2*)(dist + rowbase + (nt << 3));
                pe0[nt] = *(const float2*)(ener + rowbase + (nt << 3));
                pk0[nt] = *(const int2*)(mask + rowbase + (nt << 3));
            }
        }

        // ---- S = Q @ K^T via mma (warp slice 16 x 32) ----
        float sc[4][4];
        #pragma unroll
        for (int nt = 0; nt < 4; ++nt)
            #pragma unroll
            for (int q = 0; q < 4; ++q) sc[nt][q] = 0.f;

        #pragma unroll
        for (int kc = 0; kc < 8; ++kc) {
            int k1 = (kc << 3) + lk, k2 = k1 + 4;
            int sw1 = SWZ(k1), sw2 = SWZ(k2);
            const float* q1 = sqt + k1 * 64;
            const float* q2 = sqt + k2 * 64;
            unsigned a0 = __float_as_uint(q1[(m0 + lm) ^ sw1]);
            unsigned a1 = __float_as_uint(q1[(m0 + lm + 8) ^ sw1]);
            unsigned a2 = __float_as_uint(q2[(m0 + lm) ^ sw2]);
            unsigned a3 = __float_as_uint(q2[(m0 + lm + 8) ^ sw2]);
            const float* kp1 = skt + k1 * 64;
            const float* kp2 = skt + k2 * 64;
            #pragma unroll
            for (int nt = 0; nt < 4; ++nt) {
                int n = nc0 + (nt << 3) + lm;
                mma_tf32(sc[nt], a0, a1, a2, a3,
                         __float_as_uint(kp1[n ^ sw1]),
                         __float_as_uint(kp2[n ^ sw2]));
            }
        }

        // ---- bias (smem LUT) + mask: half 0 from prefetch, half 1 inline ----
        #pragma unroll
        for (int nt = 0; nt < 4; ++nt) {
            float v0 = sc[nt][0], v1 = sc[nt][1];
            v0 += lut_bias_s(pd0[nt].x, loD, ihD, slutD) + lut_bias_s(pe0[nt].x, loE, ihE, slutE);
            v1 += lut_bias_s(pd0[nt].y, loD, ihD, slutD) + lut_bias_s(pe0[nt].y, loE, ihE, slutE);
            sc[nt][0] = (pk0[nt].x == 0) ? -1e9f : v0;
            sc[nt][1] = (pk0[nt].y == 0) ? -1e9f : v1;
        }
        {
            size_t rowbase = ((size_t)(head * SS + i0 + m0 + lm + 8)) * SS
                           + (size_t)(j0 + nc0 + (lk << 1));
            #pragma unroll
            for (int nt = 0; nt < 4; ++nt) {
                float2 d2 = *(const float2*)(dist + rowbase + (nt << 3));
                float2 e2 = *(const float2*)(ener + rowbase + (nt << 3));
                int2  mk2 = *(const int2*)(mask + rowbase + (nt << 3));
                float v0 = sc[nt][2], v1 = sc[nt][3];
                v0 += lut_bias_s(d2.x, loD, ihD, slutD) + lut_bias_s(e2.x, loE, ihE, slutE);
                v1 += lut_bias_s(d2.y, loD, ihD, slutD) + lut_bias_s(e2.y, loE, ihE, slutE);
                sc[nt][2] = (mk2.x == 0) ? -1e9f : v0;
                sc[nt][3] = (mk2.y == 0) ? -1e9f : v1;
            }
        }

        // ---- online softmax (half-private; shfl over the 4 lk lanes) ----
        #pragma unroll
        for (int half = 0; half < 2; ++half) {
            float rmax = -1e30f;
            #pragma unroll
            for (int nt = 0; nt < 4; ++nt)
                rmax = fmaxf(rmax, fmaxf(sc[nt][(half << 1)], sc[nt][(half << 1) + 1]));
            rmax = fmaxf(rmax, __shfl_xor_sync(0xffffffffu, rmax, 1));
            rmax = fmaxf(rmax, __shfl_xor_sync(0xffffffffu, rmax, 2));
            float mnew = fmaxf(mrow[half], rmax);
            float corr = __expf(mrow[half] - mnew);
            mrow[half] = mnew;

            float rs = 0.f;
            int m = m0 + lm + (half << 3);
            #pragma unroll
            for (int nt = 0; nt < 4; ++nt) {
                float p0 = __expf(sc[nt][(half << 1)] - mnew);
                float p1 = __expf(sc[nt][(half << 1) + 1] - mnew);
                rs += p0 + p1;
                int j = nc0 + (nt << 3) + (lk << 1);
                spt[j * 64 + (m ^ SWZ(j))]           = tf32f(p0);
                spt[(j + 1) * 64 + (m ^ SWZ(j + 1))] = tf32f(p1);
            }
            rs += __shfl_xor_sync(0xffffffffu, rs, 1);
            rs += __shfl_xor_sync(0xffffffffu, rs, 2);
            lrow[half] = lrow[half] * corr + rs;
            #pragma unroll
            for (int dt = 0; dt < 8; ++dt) {
                acc[dt][(half << 1) + 0] *= corr;
                acc[dt][(half << 1) + 1] *= corr;
            }
        }
        __syncwarp();   // spt visibility within warp (warp-private region)

        // ---- acc += P @ V via mma (k-dim = warp's 32 keys, n = all 64 d) ----
        #pragma unroll
        for (int jc = 0; jc < 4; ++jc) {
            int j1 = nc0 + (jc << 3) + lk, j2 = j1 + 4;
            int sw1 = SWZ(j1), sw2 = SWZ(j2);
            const float* p1r = spt + j1 * 64;
            const float* p2r = spt + j2 * 64;
            unsigned a0 = __float_as_uint(p1r[(m0 + lm) ^ sw1]);
            unsigned a1 = __float_as_uint(p1r[(m0 + lm + 8) ^ sw1]);
            unsigned a2 = __float_as_uint(p2r[(m0 + lm) ^ sw2]);
            unsigned a3 = __float_as_uint(p2r[(m0 + lm + 8) ^ sw2]);
            const float* v1r = sv + j1 * 64;
            const float* v2r = sv + j2 * 64;
            #pragma unroll
            for (int dt = 0; dt < 8; ++dt) {
                int d = (dt << 3) + lm;
                mma_tf32(acc[dt], a0, a1, a2, a3,
                         __float_as_uint(v1r[d ^ sw1]),
                         __float_as_uint(v2r[d ^ sw2]));
            }
        }
    }

    // ---- per-CTA merge of the two wn halves, then write split partials ----
    __syncthreads();                  // all mma reads done; smem reusable
    float* accb = smem;               // [2][64][72]
    float* mlb  = smem + 9216;        // [2][2][64]
    {
        int base = wn * 4608;
        #pragma unroll
        for (int half = 0; half < 2; ++half) {
            int m = m0 + lm + (half << 3);
            #pragma unroll
            for (int dt = 0; dt < 8; ++dt)
                *(float2*)&accb[base + m * 72 + (dt << 3) + (lk << 1)] =
                    make_float2(acc[dt][(half << 1)], acc[dt][(half << 1) + 1]);
            if (lk == 0) {
                mlb[wn * 128 + m]      = mrow[half];
                mlb[wn * 128 + 64 + m] = lrow[half];
            }
        }
    }
    __syncthreads();
    {
        int row = t >> 2, ds = t & 3;
        float ma = mlb[row],       la = mlb[64 + row];
        float mb = mlb[128 + row], lb = mlb[192 + row];
        float mx = fmaxf(ma, mb);
        float ea = __expf(ma - mx), eb = __expf(mb - mx);
        float l = la * ea + lb * eb;
        int grow = i0 + row;
        #pragma unroll
        for (int q = 0; q < 4; ++q) {
            int d = (ds << 4) + (q << 2);
            float4 xa = *(const float4*)&accb[row * 72 + d];
            float4 xb = *(const float4*)&accb[4608 + row * 72 + d];
            float4 o = make_float4(xa.x * ea + xb.x * eb, xa.y * ea + xb.y * eb,
                                   xa.z * ea + xb.z * eb, xa.w * ea + xb.w * eb);
            *(float4*)&g_pacc[z][head][grow][d] = o;
        }
        if (ds == 0) { g_pm[z][head][grow] = mx; g_pl[z][head][grow] = l; }
    }

    // ---- last CTA of the (i0, head) group merges the SPLIT partials ----
    __shared__ int s_last;
    __threadfence();                  // publish this CTA's partials (all threads)
    __syncthreads();
    if (t == 0) {
        int old = atomicAdd(&g_cnt[blockIdx.x][head], 1);
        s_last = (old == SPLIT - 1) ? 1 : 0;
    }
    __syncthreads();
    if (s_last) {
        __threadfence();              // acquire: other CTAs' partials now visible
        int row = t >> 2, ds = t & 3;
        int grow = i0 + row;

        float m[SPLIT], l[SPLIT];
        float mx = -1e30f;
        #pragma unroll
        for (int zz = 0; zz < SPLIT; ++zz) {
            m[zz] = g_pm[zz][head][grow];
            l[zz] = g_pl[zz][head][grow];
            mx = fmaxf(mx, m[zz]);
        }
        float denom = 0.f;
        float a[SPLIT];
        #pragma unroll
        for (int zz = 0; zz < SPLIT; ++zz) {
            a[zz] = __expf(m[zz] - mx);
            denom = fmaf(l[zz], a[zz], denom);
        }
        float inv = 1.0f / denom;

        #pragma unroll
        for (int q = 0; q < 4; ++q) {
            int d = (ds << 4) + (q << 2);
            float4 o = make_float4(0.f, 0.f, 0.f, 0.f);
            #pragma unroll
            for (int zz = 0; zz < SPLIT; ++zz) {
                float s = a[zz] * inv;
                float4 x = *(const float4*)&g_pacc[zz][head][grow][d];
                o.x = fmaf(x.x, s, o.x);
                o.y = fmaf(x.y, s, o.y);
                o.z = fmaf(x.z, s, o.z);
                o.w = fmaf(x.w, s, o.w);
            }
            *(float4*)(out + ((size_t)(head * SS + grow) * DH) + d) = o;
        }
    }
}

// ---------------------------------------------------------------------------
// Launch
// ---------------------------------------------------------------------------
extern "C" void kernel_launch(void* const* d_in, const int* in_sizes, int n_in,
                              void* d_out, int out_size) {
    const float* Q    = (const float*)d_in[0];
    const float* K    = (const float*)d_in[1];
    const float* V    = (const float*)d_in[2];
    const float* dist = (const float*)d_in[3];
    const float* ener = (const float*)d_in[4];
    const int*   mask = (const int*)d_in[5];
    const float* muD  = (const float*)d_in[6];
    const float* sgD  = (const float*)d_in[7];
    const float* bD   = (const float*)d_in[8];
    const float* muE  = (const float*)d_in[9];
    const float* sgE  = (const float*)d_in[10];
    const float* bE   = (const float*)d_in[11];
    const float* W1   = (const float*)d_in[12];
    const float* b1   = (const float*)d_in[13];
    const float* W2   = (const float*)d_in[14];
    const float* b2   = (const float*)d_in[15];
    float* out = (float*)d_out;

    dim3 lgrid(2, LUTN / 256);
    build_lut_kernel<<<lgrid, 256>>>(muD, sgD, bD, muE, sgE, bE, W1, b1, W2, b2);

    const int smem_bytes = (16384 + 2 * LUTN) * sizeof(float);   // 80 KB
    cudaFuncSetAttribute(attn_kernel, cudaFuncAttributeMaxDynamicSharedMemorySize, smem_bytes);
    dim3 grid(SS / BM, NH, SPLIT);
    attn_kernel<<<grid, 256, smem_bytes>>>(Q, K, V, dist, ener, mask, out);
}

// round 15
// speedup vs baseline: 1.4520x; 1.4520x over previous
#include <cuda_runtime.h>
#include <cstdint>

// Problem constants (B=1, H=8, S=1024, D=64, KG=10)
#define SS    1024
#define DH    64
#define NH    8
#define NKG   10
#define LUTN  2048
#define BM    64
#define BN    64
#define SPLIT 8
#define SKEY  (SS / SPLIT)

// Octet swizzle for Q^T / V / P^T tiles (unchanged, proven conflict-free)
#define SWZ(k) ((((k) ^ ((k) >> 2)) & 3) << 3)

// ---------------------------------------------------------------------------
// Device scratch (static allocations only — no cudaMalloc allowed)
// ---------------------------------------------------------------------------
__device__ float g_lutD[LUTN];                 // plain float tables
__device__ float g_lutE[LUTN];
__device__ float g_rng[4];                     // loD, invhD, loE, invhE
__device__ float g_pacc[SPLIT][NH][SS][DH];    // 16 MB partial accumulators
__device__ float g_pm[SPLIT][NH][SS];
__device__ float g_pl[SPLIT][NH][SS];

// ---------------------------------------------------------------------------
// tf32 + mma helpers
// ---------------------------------------------------------------------------
__device__ __forceinline__ unsigned tf32_of(float x) {
    unsigned u; asm("cvt.rna.tf32.f32 %0, %1;" : "=r"(u) : "f"(x)); return u;
}
__device__ __forceinline__ float tf32f(float x) { return __uint_as_float(tf32_of(x)); }

__device__ __forceinline__ void mma_tf32(
    float* c, unsigned a0, unsigned a1, unsigned a2, unsigned a3,
    unsigned b0, unsigned b1)
{
    asm volatile(
        "mma.sync.aligned.m16n8k8.row.col.f32.tf32.tf32.f32 "
        "{%0,%1,%2,%3}, {%4,%5,%6,%7}, {%8,%9}, {%0,%1,%2,%3};"
        : "+f"(c[0]), "+f"(c[1]), "+f"(c[2]), "+f"(c[3])
        : "r"(a0), "r"(a1), "r"(a2), "r"(a3), "r"(b0), "r"(b1));
}

// smem-resident LUT interpolation: 2 LDS.32 (bank-conflict gather)
__device__ __forceinline__ float lut_bias_s(float x, float lo, float ih,
                                            const float* __restrict__ slut) {
    float u = (x - lo) * ih;
    u = fminf(fmaxf(u, 0.f), (float)(LUTN - 1));
    int ii = min((int)u, LUTN - 2);
    float fr = u - (float)ii;
    float va = slut[ii];
    float vb = slut[ii + 1];
    return fmaf(vb - va, fr, va);
}

// ---------------------------------------------------------------------------
// Kernel 1: build float bias LUTs, one grid point per thread.
// bias(x) = W2 @ gelu(W1 @ psi(x) + b1) + b2, psi_k(x) = N(x + b_k; mu_k, s_k)
// Range covers +-12 sigma of every kernel center; outside, psi underflows to
// 0 so clamping to the LUT edge is exact.
// ---------------------------------------------------------------------------
__global__ void build_lut_kernel(
    const float* __restrict__ muD, const float* __restrict__ sgD, const float* __restrict__ bD,
    const float* __restrict__ muE, const float* __restrict__ sgE, const float* __restrict__ bE,
    const float* __restrict__ W1, const float* __restrict__ b1,
    const float* __restrict__ W2, const float* __restrict__ b2)
{
    const int which = blockIdx.x;            // 0 => D, 1 => E
    const float* mu = which ? muE : muD;
    const float* sg = which ? sgE : sgD;
    const float* bb = which ? bE  : bD;
    float* lut      = which ? g_lutE : g_lutD;

    float mus[NKG], sgs[NKG], bbs[NKG], inorm[NKG];
    float lo = 1e30f, hi = -1e30f;
    #pragma unroll
    for (int k = 0; k < NKG; ++k) {
        mus[k] = __ldg(&mu[k]); sgs[k] = __ldg(&sg[k]); bbs[k] = __ldg(&bb[k]);
        inorm[k] = 0.3989422804014327f / sgs[k];
        float c = mus[k] - bbs[k];
        lo = fminf(lo, c - 12.f * sgs[k]);
        hi = fmaxf(hi, c + 12.f * sgs[k]);
    }
    float w1[NKG * NKG], bias1[NKG], w2[NKG], bias2;
    #pragma unroll
    for (int i = 0; i < NKG * NKG; ++i) w1[i] = __ldg(&W1[i]);
    #pragma unroll
    for (int i = 0; i < NKG; ++i) { bias1[i] = __ldg(&b1[i]); w2[i] = __ldg(&W2[i]); }
    bias2 = __ldg(&b2[0]);

    const float step = (hi - lo) / (float)(LUTN - 1);
    const int e = blockIdx.y * blockDim.x + threadIdx.x;   // 0..LUTN-1
    if (e < LUTN) {
        float x = lo + step * (float)e;
        float psi[NKG];
        #pragma unroll
        for (int k = 0; k < NKG; ++k) {
            float z = (x + bbs[k] - mus[k]) / sgs[k];
            psi[k] = expf(-0.5f * z * z) * inorm[k];
        }
        float f = bias2;
        #pragma unroll
        for (int l = 0; l < NKG; ++l) {
            float u = bias1[l];
            #pragma unroll
            for (int k = 0; k < NKG; ++k)
                u = fmaf(w1[l * NKG + k], psi[k], u);
            float g = 0.5f * u * (1.0f + erff(u * 0.70710678118654752f));
            f = fmaf(w2[l], g, f);
        }
        lut[e] = f;
    }
    if (e == 0) {
        float invh = (float)(LUTN - 1) / (hi - lo);
        if (which) { g_rng[2] = lo; g_rng[3] = invh; }
        else       { g_rng[0] = lo; g_rng[1] = invh; }
    }
}

// ---------------------------------------------------------------------------
// Kernel 2: tf32 tensor-core flash attention (split-KV partial) + smem LUT.
// Grid (S/BM, H, SPLIT) = (16, 8, 8). 256 threads = 8 warps in 4x2 (M x N).
// K tile in NATURAL row layout [key n][feat k], 16B-chunk swizzle
// chunk' = chunk ^ (n & 15): vector staging, conflict-free B-fragment loads.
// ---------------------------------------------------------------------------
__global__ void __launch_bounds__(256, 2) attn_kernel(
    const float* __restrict__ Q, const float* __restrict__ K, const float* __restrict__ V,
    const float* __restrict__ dist, const float* __restrict__ ener,
    const int* __restrict__ mask)
{
    extern __shared__ float smem[];
    float* sqt   = smem;             // [k=64][m=64] Q^T tf32:  k*64 + (m ^ SWZ(k))
    float* sk    = smem + 4096;      // [n=64][k=64] K natural: n*64 + chunk-swz
    float* sv    = smem + 8192;      // [j=64][d=64] V tf32:    j*64 + (d ^ SWZ(j))
    float* spt   = smem + 12288;     // [j=64][m=64] P^T tf32:  j*64 + (m ^ SWZ(j))
    float* slutD = smem + 16384;     // [2048] bias LUT D
    float* slutE = smem + 18432;     // [2048] bias LUT E

    const int t    = threadIdx.x;
    const int lane = t & 31, w = t >> 5;
    const int lk   = lane & 3, lm = lane >> 2;
    const int wm   = w & 3, wn = w >> 2;
    const int m0   = wm << 4;          // warp's row base within tile
    const int nc0  = wn << 5;          // warp's key-col base within tile
    const int head = blockIdx.y;
    const int i0   = blockIdx.x * BM;
    const int z    = blockIdx.z;

    // ---- stage LUTs into shared ----
    for (int i = t; i < LUTN; i += 256) {
        slutD[i] = g_lutD[i];
        slutE[i] = g_lutE[i];
    }

    // ---- stage Q^T (scaled, tf32) ----
    {
        const float qscale = 0.08838834764831845f;   // 1/sqrt(128)
        const float4* qg = (const float4*)(Q + (size_t)(head * SS + i0) * DH);
        for (int idx = t; idx < 1024; idx += 256) {
            int r = idx >> 4, ch = idx & 15;         // coalesced global reads
            float4 v = qg[r * 16 + ch];
            int d0 = ch << 2;
            sqt[(d0 + 0) * 64 + (r ^ SWZ(d0 + 0))] = tf32f(v.x * qscale);
            sqt[(d0 + 1) * 64 + (r ^ SWZ(d0 + 1))] = tf32f(v.y * qscale);
            sqt[(d0 + 2) * 64 + (r ^ SWZ(d0 + 2))] = tf32f(v.z * qscale);
            sqt[(d0 + 3) * 64 + (r ^ SWZ(d0 + 3))] = tf32f(v.w * qscale);
        }
    }
    const float loD = g_rng[0], ihD = g_rng[1], loE = g_rng[2], ihE = g_rng[3];

    float acc[8][4];                  // O accumulator: 8 d-tiles x C-frag
    #pragma unroll
    for (int dt = 0; dt < 8; ++dt)
        #pragma unroll
        for (int q = 0; q < 4; ++q) acc[dt][q] = 0.f;
    float mrow[2] = {-1e30f, -1e30f};   // rows lm, lm+8 (warp-half private)
    float lrow[2] = {0.f, 0.f};

    for (int jt = 0; jt < SKEY / BN; ++jt) {
        const int j0 = z * SKEY + jt * BN;
        __syncthreads();   // previous iteration's PV reads done before restaging

        // ---- stage K (natural, chunk-swizzled, vector STS) and V (tf32) ----
        {
            const float4* kg = (const float4*)(K + (size_t)(head * SS + j0) * DH);
            const float4* vg = (const float4*)(V + (size_t)(head * SS + j0) * DH);
            for (int idx = t; idx < 1024; idx += 256) {
                int r = idx >> 4, ch = idx & 15;
                float4 kv = kg[r * 16 + ch];
                float4 kt = make_float4(tf32f(kv.x), tf32f(kv.y), tf32f(kv.z), tf32f(kv.w));
                ((float4*)sk)[r * 16 + (ch ^ (r & 15))] = kt;
                float4 vv = vg[r * 16 + ch];
                float4 vt = make_float4(tf32f(vv.x), tf32f(vv.y), tf32f(vv.z), tf32f(vv.w));
                *(float4*)&sv[r * 64 + ((ch << 2) ^ SWZ(r))] = vt;
            }
        }
        __syncthreads();

        // ---- S = Q @ K^T via mma (warp slice 16 x 32) ----
        float sc[4][4];
        #pragma unroll
        for (int nt = 0; nt < 4; ++nt)
            #pragma unroll
            for (int q = 0; q < 4; ++q) sc[nt][q] = 0.f;

        #pragma unroll
        for (int kc = 0; kc < 8; ++kc) {
            int k1 = (kc << 3) + lk, k2 = k1 + 4;
            int sw1 = SWZ(k1), sw2 = SWZ(k2);
            const float* q1 = sqt + k1 * 64;
            const float* q2 = sqt + k2 * 64;
            unsigned a0 = __float_as_uint(q1[(m0 + lm) ^ sw1]);
            unsigned a1 = __float_as_uint(q1[(m0 + lm + 8) ^ sw1]);
            unsigned a2 = __float_as_uint(q2[(m0 + lm) ^ sw2]);
            unsigned a3 = __float_as_uint(q2[(m0 + lm + 8) ^ sw2]);
            const int c1 = kc << 1, c2 = (kc << 1) + 1;   // k-chunk indices
            #pragma unroll
            for (int nt = 0; nt < 4; ++nt) {
                int n = nc0 + (nt << 3) + lm;
                const float* kb = sk + n * 64;
                unsigned b0 = __float_as_uint(kb[lk | (((c1 ^ n) & 15) << 2)]);
                unsigned b1 = __float_as_uint(kb[lk | (((c2 ^ n) & 15) << 2)]);
                mma_tf32(sc[nt], a0, a1, a2, a3, b0, b1);
            }
        }

        // ---- bias (smem LUT) + mask on the C fragments ----
        #pragma unroll
        for (int half = 0; half < 2; ++half) {
            int gi = i0 + m0 + lm + (half << 3);
            size_t rowbase = ((size_t)(head * SS + gi)) * SS + (size_t)(j0 + nc0 + (lk << 1));
            #pragma unroll
            for (int nt = 0; nt < 4; ++nt) {
                float2 d2 = *(const float2*)(dist + rowbase + (nt << 3));
                float2 e2 = *(const float2*)(ener + rowbase + (nt << 3));
                int2  mk2 = *(const int2*)(mask + rowbase + (nt << 3));
                float v0 = sc[nt][(half << 1) + 0];
                float v1 = sc[nt][(half << 1) + 1];
                v0 += lut_bias_s(d2.x, loD, ihD, slutD) + lut_bias_s(e2.x, loE, ihE, slutE);
                v1 += lut_bias_s(d2.y, loD, ihD, slutD) + lut_bias_s(e2.y, loE, ihE, slutE);
                sc[nt][(half << 1) + 0] = (mk2.x == 0) ? -1e9f : v0;
                sc[nt][(half << 1) + 1] = (mk2.y == 0) ? -1e9f : v1;
            }
        }

        // ---- online softmax (half-private; shfl over the 4 lk lanes) ----
        #pragma unroll
        for (int half = 0; half < 2; ++half) {
            float rmax = -1e30f;
            #pragma unroll
            for (int nt = 0; nt < 4; ++nt)
                rmax = fmaxf(rmax, fmaxf(sc[nt][(half << 1)], sc[nt][(half << 1) + 1]));
            rmax = fmaxf(rmax, __shfl_xor_sync(0xffffffffu, rmax, 1));
            rmax = fmaxf(rmax, __shfl_xor_sync(0xffffffffu, rmax, 2));
            float mnew = fmaxf(mrow[half], rmax);
            float corr = __expf(mrow[half] - mnew);
            mrow[half] = mnew;

            float rs = 0.f;
            int m = m0 + lm + (half << 3);
            #pragma unroll
            for (int nt = 0; nt < 4; ++nt) {
                float p0 = __expf(sc[nt][(half << 1)] - mnew);
                float p1 = __expf(sc[nt][(half << 1) + 1] - mnew);
                rs += p0 + p1;
                int j = nc0 + (nt << 3) + (lk << 1);
                spt[j * 64 + (m ^ SWZ(j))]           = tf32f(p0);
                spt[(j + 1) * 64 + (m ^ SWZ(j + 1))] = tf32f(p1);
            }
            rs += __shfl_xor_sync(0xffffffffu, rs, 1);
            rs += __shfl_xor_sync(0xffffffffu, rs, 2);
            lrow[half] = lrow[half] * corr + rs;
            #pragma unroll
            for (int dt = 0; dt < 8; ++dt) {
                acc[dt][(half << 1) + 0] *= corr;
                acc[dt][(half << 1) + 1] *= corr;
            }
        }
        __syncwarp();   // spt visibility within warp (warp-private region)

        // ---- acc += P @ V via mma (k-dim = warp's 32 keys, n = all 64 d) ----
        #pragma unroll
        for (int jc = 0; jc < 4; ++jc) {
            int j1 = nc0 + (jc << 3) + lk, j2 = j1 + 4;
            int sw1 = SWZ(j1), sw2 = SWZ(j2);
            const float* p1r = spt + j1 * 64;
            const float* p2r = spt + j2 * 64;
            unsigned a0 = __float_as_uint(p1r[(m0 + lm) ^ sw1]);
            unsigned a1 = __float_as_uint(p1r[(m0 + lm + 8) ^ sw1]);
            unsigned a2 = __float_as_uint(p2r[(m0 + lm) ^ sw2]);
            unsigned a3 = __float_as_uint(p2r[(m0 + lm + 8) ^ sw2]);
            const float* v1r = sv + j1 * 64;
            const float* v2r = sv + j2 * 64;
            #pragma unroll
            for (int dt = 0; dt < 8; ++dt) {
                int d = (dt << 3) + lm;
                mma_tf32(acc[dt], a0, a1, a2, a3,
                         __float_as_uint(v1r[d ^ sw1]),
                         __float_as_uint(v2r[d ^ sw2]));
            }
        }
    }

    // ---- per-CTA merge of the two wn halves, then write split partials ----
    __syncthreads();                  // all mma reads done; smem reusable
    float* accb = smem;               // [2][64][72]
    float* mlb  = smem + 9216;        // [2][2][64]
    {
        int base = wn * 4608;
        #pragma unroll
        for (int half = 0; half < 2; ++half) {
            int m = m0 + lm + (half << 3);
            #pragma unroll
            for (int dt = 0; dt < 8; ++dt)
                *(float2*)&accb[base + m * 72 + (dt << 3) + (lk << 1)] =
                    make_float2(acc[dt][(half << 1)], acc[dt][(half << 1) + 1]);
            if (lk == 0) {
                mlb[wn * 128 + m]      = mrow[half];
                mlb[wn * 128 + 64 + m] = lrow[half];
            }
        }
    }
    __syncthreads();
    {
        int row = t >> 2, ds = t & 3;
        float ma = mlb[row],       la = mlb[64 + row];
        float mb = mlb[128 + row], lb = mlb[192 + row];
        float mx = fmaxf(ma, mb);
        float ea = __expf(ma - mx), eb = __expf(mb - mx);
        float l = la * ea + lb * eb;
        int grow = i0 + row;
        #pragma unroll
        for (int q = 0; q < 4; ++q) {
            int d = (ds << 4) + (q << 2);
            float4 xa = *(const float4*)&accb[row * 72 + d];
            float4 xb = *(const float4*)&accb[4608 + row * 72 + d];
            float4 o = make_float4(xa.x * ea + xb.x * eb, xa.y * ea + xb.y * eb,
                                   xa.z * ea + xb.z * eb, xa.w * ea + xb.w * eb);
            *(float4*)&g_pacc[z][head][grow][d] = o;
        }
        if (ds == 0) { g_pm[z][head][grow] = mx; g_pl[z][head][grow] = l; }
    }
}

// ---------------------------------------------------------------------------
// Kernel 3: merge the SPLIT partials.
// ---------------------------------------------------------------------------
__global__ void merge_kernel(float* __restrict__ out)
{
    int idx = blockIdx.x * blockDim.x + threadIdx.x;   // over NH*SS*(DH/4)
    int d4  = idx & (DH / 4 - 1);
    int rh  = idx >> 4;
    int row = rh & (SS - 1);
    int h   = rh >> 10;

    float m[SPLIT], l[SPLIT];
    float mx = -1e30f;
    #pragma unroll
    for (int zz = 0; zz < SPLIT; ++zz) {
        m[zz] = g_pm[zz][h][row];
        l[zz] = g_pl[zz][h][row];
        mx = fmaxf(mx, m[zz]);
    }
    float denom = 0.f;
    float a[SPLIT];
    #pragma unroll
    for (int zz = 0; zz < SPLIT; ++zz) {
        a[zz] = __expf(m[zz] - mx);
        denom = fmaf(l[zz], a[zz], denom);
    }
    float inv = 1.0f / denom;

    float4 o = make_float4(0.f, 0.f, 0.f, 0.f);
    #pragma unroll
    for (int zz = 0; zz < SPLIT; ++zz) {
        float s = a[zz] * inv;
        float4 x = *(const float4*)&g_pacc[zz][h][row][d4 << 2];
        o.x = fmaf(x.x, s, o.x);
        o.y = fmaf(x.y, s, o.y);
        o.z = fmaf(x.z, s, o.z);
        o.w = fmaf(x.w, s, o.w);
    }
    *(float4*)(out + ((size_t)(h * SS + row) * DH) + (d4 << 2)) = o;
}

// ---------------------------------------------------------------------------
// Launch
// ---------------------------------------------------------------------------
extern "C" void kernel_launch(void* const* d_in, const int* in_sizes, int n_in,
                              void* d_out, int out_size) {
    const float* Q    = (const float*)d_in[0];
    const float* K    = (const float*)d_in[1];
    const float* V    = (const float*)d_in[2];
    const float* dist = (const float*)d_in[3];
    const float* ener = (const float*)d_in[4];
    const int*   mask = (const int*)d_in[5];
    const float* muD  = (const float*)d_in[6];
    const float* sgD  = (const float*)d_in[7];
    const float* bD   = (const float*)d_in[8];
    const float* muE  = (const float*)d_in[9];
    const float* sgE  = (const float*)d_in[10];
    const float* bE   = (const float*)d_in[11];
    const float* W1   = (const float*)d_in[12];
    const float* b1   = (const float*)d_in[13];
    const float* W2   = (const float*)d_in[14];
    const float* b2   = (const float*)d_in[15];
    float* out = (float*)d_out;

    dim3 lgrid(2, LUTN / 256);
    build_lut_kernel<<<lgrid, 256>>>(muD, sgD, bD, muE, sgE, bE, W1, b1, W2, b2);

    const int smem_bytes = (16384 + 2 * LUTN) * sizeof(float);   // 80 KB
    cudaFuncSetAttribute(attn_kernel, cudaFuncAttributeMaxDynamicSharedMemorySize, smem_bytes);
    dim3 grid(SS / BM, NH, SPLIT);
    attn_kernel<<<grid, 256, smem_bytes>>>(Q, K, V, dist, ener, mask);

    merge_kernel<<<NH * SS * (DH / 4) / 256, 256>>>(out);
}

// round 16
// speedup vs baseline: 1.5975x; 1.1002x over previous
#include <cuda_runtime.h>
#include <cstdint>

// Problem constants (B=1, H=8, S=1024, D=64, KG=10)
#define SS    1024
#define DH    64
#define NH    8
#define NKG   10
#define LUTN  2048
#define BM    64
#define BN    64
#define SPLIT 8
#define SKEY  (SS / SPLIT)

// Octet swizzle for Q^T / V / P^T tiles (proven conflict-free)
#define SWZ(k) ((((k) ^ ((k) >> 2)) & 3) << 3)

// ---------------------------------------------------------------------------
// Device scratch (static allocations only — no cudaMalloc allowed)
// ---------------------------------------------------------------------------
__device__ float g_lutD[LUTN];                 // plain float tables
__device__ float g_lutE[LUTN];
__device__ float g_rng[4];                     // loD, invhD, loE, invhE
__device__ float g_pacc[SPLIT][NH][SS][DH];    // 16 MB partial accumulators
__device__ float g_pm[SPLIT][NH][SS];
__device__ float g_pl[SPLIT][NH][SS];

// ---------------------------------------------------------------------------
// tf32 + mma helpers
// ---------------------------------------------------------------------------
__device__ __forceinline__ unsigned tf32_of(float x) {
    unsigned u; asm("cvt.rna.tf32.f32 %0, %1;" : "=r"(u) : "f"(x)); return u;
}
__device__ __forceinline__ float tf32f(float x) { return __uint_as_float(tf32_of(x)); }

__device__ __forceinline__ void mma_tf32(
    float* c, unsigned a0, unsigned a1, unsigned a2, unsigned a3,
    unsigned b0, unsigned b1)
{
    asm volatile(
        "mma.sync.aligned.m16n8k8.row.col.f32.tf32.tf32.f32 "
        "{%0,%1,%2,%3}, {%4,%5,%6,%7}, {%8,%9}, {%0,%1,%2,%3};"
        : "+f"(c[0]), "+f"(c[1]), "+f"(c[2]), "+f"(c[3])
        : "r"(a0), "r"(a1), "r"(a2), "r"(a3), "r"(b0), "r"(b1));
}

// smem-resident LUT interpolation: 2 LDS.32 (bank-conflict gather)
__device__ __forceinline__ float lut_bias_s(float x, float lo, float ih,
                                            const float* __restrict__ slut) {
    float u = (x - lo) * ih;
    u = fminf(fmaxf(u, 0.f), (float)(LUTN - 1));
    int ii = min((int)u, LUTN - 2);
    float fr = u - (float)ii;
    float va = slut[ii];
    float vb = slut[ii + 1];
    return fmaf(vb - va, fr, va);
}

// ---------------------------------------------------------------------------
// Kernel 1: build float bias LUTs. TWO threads per LUT entry: each evaluates
// psi, then half of the 10 hidden units (5 erff chains); partials combined
// with one shfl. Halves the serial-latency chain of the old version.
// bias(x) = W2 @ gelu(W1 @ psi(x) + b1) + b2, psi_k(x) = N(x + b_k; mu_k, s_k)
// Range covers +-12 sigma of every kernel center; outside, psi underflows to
// 0 so clamping to the LUT edge is exact.
// ---------------------------------------------------------------------------
__global__ void build_lut_kernel(
    const float* __restrict__ muD, const float* __restrict__ sgD, const float* __restrict__ bD,
    const float* __restrict__ muE, const float* __restrict__ sgE, const float* __restrict__ bE,
    const float* __restrict__ W1, const float* __restrict__ b1,
    const float* __restrict__ W2, const float* __restrict__ b2)
{
    const int which = blockIdx.x;            // 0 => D, 1 => E
    const float* mu = which ? muE : muD;
    const float* sg = which ? sgE : sgD;
    const float* bb = which ? bE  : bD;
    float* lut      = which ? g_lutE : g_lutD;

    float mus[NKG], sgs[NKG], bbs[NKG], inorm[NKG];
    float lo = 1e30f, hi = -1e30f;
    #pragma unroll
    for (int k = 0; k < NKG; ++k) {
        mus[k] = __ldg(&mu[k]); sgs[k] = __ldg(&sg[k]); bbs[k] = __ldg(&bb[k]);
        inorm[k] = 0.3989422804014327f / sgs[k];
        float c = mus[k] - bbs[k];
        lo = fminf(lo, c - 12.f * sgs[k]);
        hi = fmaxf(hi, c + 12.f * sgs[k]);
    }

    const int gt   = blockIdx.y * blockDim.x + threadIdx.x;  // 0..2*LUTN-1
    const int e    = gt >> 1;
    const int part = gt & 1;                                 // which half of l

    float w1[5 * NKG], bias1[5], w2[5];
    const int l0 = part * 5;
    #pragma unroll
    for (int l = 0; l < 5; ++l) {
        #pragma unroll
        for (int k = 0; k < NKG; ++k) w1[l * NKG + k] = __ldg(&W1[(l0 + l) * NKG + k]);
        bias1[l] = __ldg(&b1[l0 + l]);
        w2[l]    = __ldg(&W2[l0 + l]);
    }
    float bias2 = __ldg(&b2[0]);

    const float step = (hi - lo) / (float)(LUTN - 1);
    if (e < LUTN) {
        float x = lo + step * (float)e;
        float psi[NKG];
        #pragma unroll
        for (int k = 0; k < NKG; ++k) {
            float z = (x + bbs[k] - mus[k]) / sgs[k];
            psi[k] = expf(-0.5f * z * z) * inorm[k];
        }
        float f = 0.f;
        #pragma unroll
        for (int l = 0; l < 5; ++l) {
            float u = bias1[l];
            #pragma unroll
            for (int k = 0; k < NKG; ++k)
                u = fmaf(w1[l * NKG + k], psi[k], u);
            float g = 0.5f * u * (1.0f + erff(u * 0.70710678118654752f));
            f = fmaf(w2[l], g, f);
        }
        f += __shfl_xor_sync(0xffffffffu, f, 1);   // combine the two l-halves
        if (part == 0) lut[e] = f + bias2;
    }
    if (gt == 0) {
        float invh = (float)(LUTN - 1) / (hi - lo);
        if (which) { g_rng[2] = lo; g_rng[3] = invh; }
        else       { g_rng[0] = lo; g_rng[1] = invh; }
    }
}

// ---------------------------------------------------------------------------
// Kernel 2: tf32 tensor-core flash attention (split-KV partial) + smem LUT
// + half-0 bias prefetch (hide DRAM latency under the QK mma chain).
// Grid (S/BM, H, SPLIT) = (16, 8, 8). 256 threads = 8 warps in 4x2 (M x N).
// K tile in NATURAL row layout [key n][feat k], 16B-chunk swizzle
// chunk' = chunk ^ (n & 15): vector staging, conflict-free B-fragment loads.
// ---------------------------------------------------------------------------
__global__ void __launch_bounds__(256, 2) attn_kernel(
    const float* __restrict__ Q, const float* __restrict__ K, const float* __restrict__ V,
    const float* __restrict__ dist, const float* __restrict__ ener,
    const int* __restrict__ mask)
{
    extern __shared__ float smem[];
    float* sqt   = smem;             // [k=64][m=64] Q^T tf32:  k*64 + (m ^ SWZ(k))
    float* sk    = smem + 4096;      // [n=64][k=64] K natural: n*64 + chunk-swz
    float* sv    = smem + 8192;      // [j=64][d=64] V tf32:    j*64 + (d ^ SWZ(j))
    float* spt   = smem + 12288;     // [j=64][m=64] P^T tf32:  j*64 + (m ^ SWZ(j))
    float* slutD = smem + 16384;     // [2048] bias LUT D
    float* slutE = smem + 18432;     // [2048] bias LUT E

    const int t    = threadIdx.x;
    const int lane = t & 31, w = t >> 5;
    const int lk   = lane & 3, lm = lane >> 2;
    const int wm   = w & 3, wn = w >> 2;
    const int m0   = wm << 4;          // warp's row base within tile
    const int nc0  = wn << 5;          // warp's key-col base within tile
    const int head = blockIdx.y;
    const int i0   = blockIdx.x * BM;
    const int z    = blockIdx.z;

    // ---- stage LUTs into shared (vectorized) ----
    {
        float4* sD = (float4*)slutD;
        float4* sE = (float4*)slutE;
        const float4* gD = (const float4*)g_lutD;
        const float4* gE = (const float4*)g_lutE;
        for (int i = t; i < LUTN / 4; i += 256) {
            sD[i] = gD[i];
            sE[i] = gE[i];
        }
    }

    // ---- stage Q^T (scaled, tf32) ----
    {
        const float qscale = 0.08838834764831845f;   // 1/sqrt(128)
        const float4* qg = (const float4*)(Q + (size_t)(head * SS + i0) * DH);
        for (int idx = t; idx < 1024; idx += 256) {
            int r = idx >> 4, ch = idx & 15;         // coalesced global reads
            float4 v = qg[r * 16 + ch];
            int d0 = ch << 2;
            sqt[(d0 + 0) * 64 + (r ^ SWZ(d0 + 0))] = tf32f(v.x * qscale);
            sqt[(d0 + 1) * 64 + (r ^ SWZ(d0 + 1))] = tf32f(v.y * qscale);
            sqt[(d0 + 2) * 64 + (r ^ SWZ(d0 + 2))] = tf32f(v.z * qscale);
            sqt[(d0 + 3) * 64 + (r ^ SWZ(d0 + 3))] = tf32f(v.w * qscale);
        }
    }
    const float loD = g_rng[0], ihD = g_rng[1], loE = g_rng[2], ihE = g_rng[3];

    float acc[8][4];                  // O accumulator: 8 d-tiles x C-frag
    #pragma unroll
    for (int dt = 0; dt < 8; ++dt)
        #pragma unroll
        for (int q = 0; q < 4; ++q) acc[dt][q] = 0.f;
    float mrow[2] = {-1e30f, -1e30f};   // rows lm, lm+8 (warp-half private)
    float lrow[2] = {0.f, 0.f};

    for (int jt = 0; jt < SKEY / BN; ++jt) {
        const int j0 = z * SKEY + jt * BN;
        __syncthreads();   // previous iteration's PV reads done before restaging

        // ---- stage K (natural, chunk-swizzled, vector STS) and V (tf32) ----
        {
            const float4* kg = (const float4*)(K + (size_t)(head * SS + j0) * DH);
            const float4* vg = (const float4*)(V + (size_t)(head * SS + j0) * DH);
            for (int idx = t; idx < 1024; idx += 256) {
                int r = idx >> 4, ch = idx & 15;
                float4 kv = kg[r * 16 + ch];
                float4 kt = make_float4(tf32f(kv.x), tf32f(kv.y), tf32f(kv.z), tf32f(kv.w));
                ((float4*)sk)[r * 16 + (ch ^ (r & 15))] = kt;
                float4 vv = vg[r * 16 + ch];
                float4 vt = make_float4(tf32f(vv.x), tf32f(vv.y), tf32f(vv.z), tf32f(vv.w));
                *(float4*)&sv[r * 64 + ((ch << 2) ^ SWZ(r))] = vt;
            }
        }
        __syncthreads();

        // ---- prefetch half-0 bias operands (hide DRAM latency under mma) ----
        float2 pd0[4], pe0[4];
        int2   pk0[4];
        {
            size_t rowbase = ((size_t)(head * SS + i0 + m0 + lm)) * SS
                           + (size_t)(j0 + nc0 + (lk << 1));
            #pragma unroll
            for (int nt = 0; nt < 4; ++nt) {
                pd0[nt] = *(const float2*)(dist + rowbase + (nt << 3));
                pe0[nt] = *(const float2*)(ener + rowbase + (nt << 3));
                pk0[nt] = *(const int2*)(mask + rowbase + (nt << 3));
            }
        }

        // ---- S = Q @ K^T via mma (warp slice 16 x 32) ----
        float sc[4][4];
        #pragma unroll
        for (int nt = 0; nt < 4; ++nt)
            #pragma unroll
            for (int q = 0; q < 4; ++q) sc[nt][q] = 0.f;

        #pragma unroll
        for (int kc = 0; kc < 8; ++kc) {
            int k1 = (kc << 3) + lk, k2 = k1 + 4;
            int sw1 = SWZ(k1), sw2 = SWZ(k2);
            const float* q1 = sqt + k1 * 64;
            const float* q2 = sqt + k2 * 64;
            unsigned a0 = __float_as_uint(q1[(m0 + lm) ^ sw1]);
            unsigned a1 = __float_as_uint(q1[(m0 + lm + 8) ^ sw1]);
            unsigned a2 = __float_as_uint(q2[(m0 + lm) ^ sw2]);
            unsigned a3 = __float_as_uint(q2[(m0 + lm + 8) ^ sw2]);
            const int c1 = kc << 1, c2 = (kc << 1) + 1;   // k-chunk indices
            #pragma unroll
            for (int nt = 0; nt < 4; ++nt) {
                int n = nc0 + (nt << 3) + lm;
                const float* kb = sk + n * 64;
                unsigned b0 = __float_as_uint(kb[lk | (((c1 ^ n) & 15) << 2)]);
                unsigned b1 = __float_as_uint(kb[lk | (((c2 ^ n) & 15) << 2)]);
                mma_tf32(sc[nt], a0, a1, a2, a3, b0, b1);
            }
        }

        // ---- bias (smem LUT) + mask: half 0 from prefetch, half 1 inline ----
        #pragma unroll
        for (int nt = 0; nt < 4; ++nt) {
            float v0 = sc[nt][0], v1 = sc[nt][1];
            v0 += lut_bias_s(pd0[nt].x, loD, ihD, slutD) + lut_bias_s(pe0[nt].x, loE, ihE, slutE);
            v1 += lut_bias_s(pd0[nt].y, loD, ihD, slutD) + lut_bias_s(pe0[nt].y, loE, ihE, slutE);
            sc[nt][0] = (pk0[nt].x == 0) ? -1e9f : v0;
            sc[nt][1] = (pk0[nt].y == 0) ? -1e9f : v1;
        }
        {
            size_t rowbase = ((size_t)(head * SS + i0 + m0 + lm + 8)) * SS
                           + (size_t)(j0 + nc0 + (lk << 1));
            #pragma unroll
            for (int nt = 0; nt < 4; ++nt) {
                float2 d2 = *(const float2*)(dist + rowbase + (nt << 3));
                float2 e2 = *(const float2*)(ener + rowbase + (nt << 3));
                int2  mk2 = *(const int2*)(mask + rowbase + (nt << 3));
                float v0 = sc[nt][2], v1 = sc[nt][3];
                v0 += lut_bias_s(d2.x, loD, ihD, slutD) + lut_bias_s(e2.x, loE, ihE, slutE);
                v1 += lut_bias_s(d2.y, loD, ihD, slutD) + lut_bias_s(e2.y, loE, ihE, slutE);
                sc[nt][2] = (mk2.x == 0) ? -1e9f : v0;
                sc[nt][3] = (mk2.y == 0) ? -1e9f : v1;
            }
        }

        // ---- online softmax (half-private; shfl over the 4 lk lanes) ----
        #pragma unroll
        for (int half = 0; half < 2; ++half) {
            float rmax = -1e30f;
            #pragma unroll
            for (int nt = 0; nt < 4; ++nt)
                rmax = fmaxf(rmax, fmaxf(sc[nt][(half << 1)], sc[nt][(half << 1) + 1]));
            rmax = fmaxf(rmax, __shfl_xor_sync(0xffffffffu, rmax, 1));
            rmax = fmaxf(rmax, __shfl_xor_sync(0xffffffffu, rmax, 2));
            float mnew = fmaxf(mrow[half], rmax);
            float corr = __expf(mrow[half] - mnew);
            mrow[half] = mnew;

            float rs = 0.f;
            int m = m0 + lm + (half << 3);
            #pragma unroll
            for (int nt = 0; nt < 4; ++nt) {
                float p0 = __expf(sc[nt][(half << 1)] - mnew);
                float p1 = __expf(sc[nt][(half << 1) + 1] - mnew);
                rs += p0 + p1;
                int j = nc0 + (nt << 3) + (lk << 1);
                spt[j * 64 + (m ^ SWZ(j))]           = tf32f(p0);
                spt[(j + 1) * 64 + (m ^ SWZ(j + 1))] = tf32f(p1);
            }
            rs += __shfl_xor_sync(0xffffffffu, rs, 1);
            rs += __shfl_xor_sync(0xffffffffu, rs, 2);
            lrow[half] = lrow[half] * corr + rs;
            #pragma unroll
            for (int dt = 0; dt < 8; ++dt) {
                acc[dt][(half << 1) + 0] *= corr;
                acc[dt][(half << 1) + 1] *= corr;
            }
        }
        __syncwarp();   // spt visibility within warp (warp-private region)

        // ---- acc += P @ V via mma (k-dim = warp's 32 keys, n = all 64 d) ----
        #pragma unroll
        for (int jc = 0; jc < 4; ++jc) {
            int j1 = nc0 + (jc << 3) + lk, j2 = j1 + 4;
            int sw1 = SWZ(j1), sw2 = SWZ(j2);
            const float* p1r = spt + j1 * 64;
            const float* p2r = spt + j2 * 64;
            unsigned a0 = __float_as_uint(p1r[(m0 + lm) ^ sw1]);
            unsigned a1 = __float_as_uint(p1r[(m0 + lm + 8) ^ sw1]);
            unsigned a2 = __float_as_uint(p2r[(m0 + lm) ^ sw2]);
            unsigned a3 = __float_as_uint(p2r[(m0 + lm + 8) ^ sw2]);
            const float* v1r = sv + j1 * 64;
            const float* v2r = sv + j2 * 64;
            #pragma unroll
            for (int dt = 0; dt < 8; ++dt) {
                int d = (dt << 3) + lm;
                mma_tf32(acc[dt], a0, a1, a2, a3,
                         __float_as_uint(v1r[d ^ sw1]),
                         __float_as_uint(v2r[d ^ sw2]));
            }
        }
    }

    // ---- per-CTA merge of the two wn halves, then write split partials ----
    __syncthreads();                  // all mma reads done; smem reusable
    float* accb = smem;               // [2][64][72]
    float* mlb  = smem + 9216;        // [2][2][64]
    {
        int base = wn * 4608;
        #pragma unroll
        for (int half = 0; half < 2; ++half) {
            int m = m0 + lm + (half << 3);
            #pragma unroll
            for (int dt = 0; dt < 8; ++dt)
                *(float2*)&accb[base + m * 72 + (dt << 3) + (lk << 1)] =
                    make_float2(acc[dt][(half << 1)], acc[dt][(half << 1) + 1]);
            if (lk == 0) {
                mlb[wn * 128 + m]      = mrow[half];
                mlb[wn * 128 + 64 + m] = lrow[half];
            }
        }
    }
    __syncthreads();
    {
        int row = t >> 2, ds = t & 3;
        float ma = mlb[row],       la = mlb[64 + row];
        float mb = mlb[128 + row], lb = mlb[192 + row];
        float mx = fmaxf(ma, mb);
        float ea = __expf(ma - mx), eb = __expf(mb - mx);
        float l = la * ea + lb * eb;
        int grow = i0 + row;
        #pragma unroll
        for (int q = 0; q < 4; ++q) {
            int d = (ds << 4) + (q << 2);
            float4 xa = *(const float4*)&accb[row * 72 + d];
            float4 xb = *(const float4*)&accb[4608 + row * 72 + d];
            float4 o = make_float4(xa.x * ea + xb.x * eb, xa.y * ea + xb.y * eb,
                                   xa.z * ea + xb.z * eb, xa.w * ea + xb.w * eb);
            *(float4*)&g_pacc[z][head][grow][d] = o;
        }
        if (ds == 0) { g_pm[z][head][grow] = mx; g_pl[z][head][grow] = l; }
    }
}

// ---------------------------------------------------------------------------
// Kernel 3: merge the SPLIT partials.
// ---------------------------------------------------------------------------
__global__ void merge_kernel(float* __restrict__ out)
{
    int idx = blockIdx.x * blockDim.x + threadIdx.x;   // over NH*SS*(DH/4)
    int d4  = idx & (DH / 4 - 1);
    int rh  = idx >> 4;
    int row = rh & (SS - 1);
    int h   = rh >> 10;

    float m[SPLIT], l[SPLIT];
    float mx = -1e30f;
    #pragma unroll
    for (int zz = 0; zz < SPLIT; ++zz) {
        m[zz] = g_pm[zz][h][row];
        l[zz] = g_pl[zz][h][row];
        mx = fmaxf(mx, m[zz]);
    }
    float denom = 0.f;
    float a[SPLIT];
    #pragma unroll
    for (int zz = 0; zz < SPLIT; ++zz) {
        a[zz] = __expf(m[zz] - mx);
        denom = fmaf(l[zz], a[zz], denom);
    }
    float inv = 1.0f / denom;

    float4 o = make_float4(0.f, 0.f, 0.f, 0.f);
    #pragma unroll
    for (int zz = 0; zz < SPLIT; ++zz) {
        float s = a[zz] * inv;
        float4 x = *(const float4*)&g_pacc[zz][h][row][d4 << 2];
        o.x = fmaf(x.x, s, o.x);
        o.y = fmaf(x.y, s, o.y);
        o.z = fmaf(x.z, s, o.z);
        o.w = fmaf(x.w, s, o.w);
    }
    *(float4*)(out + ((size_t)(h * SS + row) * DH) + (d4 << 2)) = o;
}

// ---------------------------------------------------------------------------
// Launch
// ---------------------------------------------------------------------------
extern "C" void kernel_launch(void* const* d_in, const int* in_sizes, int n_in,
                              void* d_out, int out_size) {
    const float* Q    = (const float*)d_in[0];
    const float* K    = (const float*)d_in[1];
    const float* V    = (const float*)d_in[2];
    const float* dist = (const float*)d_in[3];
    const float* ener = (const float*)d_in[4];
    const int*   mask = (const int*)d_in[5];
    const float* muD  = (const float*)d_in[6];
    const float* sgD  = (const float*)d_in[7];
    const float* bD   = (const float*)d_in[8];
    const float* muE  = (const float*)d_in[9];
    const float* sgE  = (const float*)d_in[10];
    const float* bE   = (const float*)d_in[11];
    const float* W1   = (const float*)d_in[12];
    const float* b1   = (const float*)d_in[13];
    const float* W2   = (const float*)d_in[14];
    const float* b2   = (const float*)d_in[15];
    float* out = (float*)d_out;

    dim3 lgrid(2, 2 * LUTN / 256);
    build_lut_kernel<<<lgrid, 256>>>(muD, sgD, bD, muE, sgE, bE, W1, b1, W2, b2);

    const int smem_bytes = (16384 + 2 * LUTN) * sizeof(float);   // 80 KB
    cudaFuncSetAttribute(attn_kernel, cudaFuncAttributeMaxDynamicSharedMemorySize, smem_bytes);
    dim3 grid(SS / BM, NH, SPLIT);
    attn_kernel<<<grid, 256, smem_bytes>>>(Q, K, V, dist, ener, mask);

    merge_kernel<<<NH * SS * (DH / 4) / 256, 256>>>(out);
}